// round 15
// baseline (speedup 1.0000x reference)
#include <cuda_runtime.h>
#include <cuda_fp16.h>
#include <math.h>
#include <stdint.h>

// ---------------------------------------------------------------------------
// Problem constants (Qwen3.5 GatedDeltaNet): B=2, T=4096, D=2048
// ---------------------------------------------------------------------------
#define BATCH   2
#define TLEN    4096
#define BT      8192
#define DMODEL  2048
#define NVH     32
#define NKH     16
#define DK      128
#define DV      128
#define KEYDIM  (NKH*DK)                 // 2048
#define VALDIM  (NVH*DV)                 // 4096
#define CONVDIM (2*KEYDIM + VALDIM)      // 8192
#define QB_N    (CONVDIM + 64)           // 8256 : [qkv | b | a]
#define QBT_NP  8320                     // padded for B tiles
#define B2_OFF  CONVDIM
#define A2_OFF  (CONVDIM + 32)
#define NCHUNK  4
#define TC      (TLEN/NCHUNK)            // 1024 t-steps per chunk

// ---------------------------------------------------------------------------
// Scratch (static device globals)
// ---------------------------------------------------------------------------
__device__ float  g_qkvba[(size_t)BT * QB_N];
__device__ float  g_z[(size_t)BT * VALDIM];
__device__ float  g_q[(size_t)BT * KEYDIM];
__device__ float  g_k[(size_t)BT * KEYDIM];
__device__ float  g_v[(size_t)BT * VALDIM];
__device__ float  g_beta[BT * NVH];
__device__ float  g_decay[BT * NVH];
__device__ float  g_o[(size_t)BT * VALDIM];
__device__ float  g_S[(size_t)128 * 64 * 128];          // scan state checkpoints
// half-precision GEMM operands
__device__ __half g_hs_h[(size_t)BT * DMODEL];
__device__ __half g_wqkvbaT[(size_t)QBT_NP * DMODEL];   // [N,K]
__device__ __half g_wzT[(size_t)VALDIM * DMODEL];       // [N,K]
__device__ __half g_woutT[(size_t)DMODEL * VALDIM];     // [N,K]
__device__ __half g_oh[(size_t)BT * VALDIM];            // gated o, half

// ---------------------------------------------------------------------------
// Packed f32x2 helpers (sm_100+)
// ---------------------------------------------------------------------------
__device__ __forceinline__ unsigned long long pack2(float x, float y) {
    unsigned long long r;
    asm("mov.b64 %0, {%1, %2};" : "=l"(r) : "f"(x), "f"(y));
    return r;
}
__device__ __forceinline__ void unpack2(unsigned long long v, float& x, float& y) {
    asm("mov.b64 {%0, %1}, %2;" : "=f"(x), "=f"(y) : "l"(v));
}
__device__ __forceinline__ unsigned long long fma2(unsigned long long a,
                                                   unsigned long long b,
                                                   unsigned long long c) {
    unsigned long long d;
    asm("fma.rn.f32x2 %0, %1, %2, %3;" : "=l"(d) : "l"(a), "l"(b), "l"(c));
    return d;
}
__device__ __forceinline__ unsigned long long mul2(unsigned long long a,
                                                   unsigned long long b) {
    unsigned long long d;
    asm("mul.rn.f32x2 %0, %1, %2;" : "=l"(d) : "l"(a), "l"(b));
    return d;
}

// ---------------------------------------------------------------------------
// FP16 tensor-core GEMM (mma.sync m16n8k16, fp32 accum)
// ---------------------------------------------------------------------------
#define TSTAGES 3
#define TBM 128
#define TBN 128
#define TBK 32
#define LDA_H 40
#define TILE_H (128*LDA_H)
#define STAGE_B (2*TILE_H*2)
#define GEMM_SMEM (TSTAGES*STAGE_B)
#define GROUP_M 8

__device__ __forceinline__ void cp16h(uint32_t dst, const __half* src) {
    asm volatile("cp.async.cg.shared.global [%0], [%1], 16;" :: "r"(dst), "l"(src));
}

__device__ __forceinline__ void ldsm_x4(uint32_t* r, uint32_t addr) {
    asm volatile("ldmatrix.sync.aligned.m8n8.x4.shared.b16 {%0,%1,%2,%3}, [%4];"
        : "=r"(r[0]), "=r"(r[1]), "=r"(r[2]), "=r"(r[3]) : "r"(addr));
}

__device__ __forceinline__ void mma_f16(float* c, const uint32_t* a, const uint32_t* b) {
    asm volatile(
        "mma.sync.aligned.m16n8k16.row.col.f32.f16.f16.f32 "
        "{%0,%1,%2,%3}, {%4,%5,%6,%7}, {%8,%9}, {%0,%1,%2,%3};"
        : "+f"(c[0]), "+f"(c[1]), "+f"(c[2]), "+f"(c[3])
        : "r"(a[0]), "r"(a[1]), "r"(a[2]), "r"(a[3]), "r"(b[0]), "r"(b[1]));
}

__global__ __launch_bounds__(256, 2) void gemm_f16_kernel(
    const __half* __restrict__ A, const __half* __restrict__ BTm,
    float* __restrict__ C, int M, int N, int K)
{
    extern __shared__ char smem[];
    const uint32_t sbase = (uint32_t)__cvta_generic_to_shared(smem);

    const int num_bm = M / TBM;
    const int num_bn = (N + TBN - 1) / TBN;
    const int pid    = blockIdx.x;
    const int ppg    = GROUP_M * num_bn;
    const int gid    = pid / ppg;
    const int fbm    = gid * GROUP_M;
    const int gsz    = min(GROUP_M, num_bm - fbm);
    const int bm     = fbm + (pid % ppg) % gsz;
    const int bn     = (pid % ppg) / gsz;

    const int tid  = threadIdx.x;
    const int warp = tid >> 5;
    const int lane = tid & 31;
    const int g    = lane >> 2;
    const int tig  = lane & 3;
    const int wm   = (warp >> 2) * 64;
    const int wn   = (warp & 3) * 32;

    float acc[4][4][4];
#pragma unroll
    for (int i = 0; i < 4; i++)
#pragma unroll
        for (int j = 0; j < 4; j++)
#pragma unroll
            for (int r = 0; r < 4; r++) acc[i][j][r] = 0.f;

    const int KT = K / TBK;

    const uint32_t a_lm_off =
        (uint32_t)(((wm + (lane & 7) + 8 * ((lane >> 3) & 1)) * LDA_H + (lane >> 4) * 8) * 2);

    auto load_stage = [&](int s, int kt) {
        uint32_t abase = sbase + (uint32_t)(s * STAGE_B);
        uint32_t bbase = abase + (uint32_t)(TILE_H * 2);
        const __half* Asrc = A   + (size_t)(bm * TBM) * K + kt * TBK;
        const __half* Bsrc = BTm + (size_t)(bn * TBN) * K + kt * TBK;
#pragma unroll
        for (int h = 0; h < 2; h++) {
            int id  = tid + h * 256;
            int row = id >> 2, c = id & 3;
            cp16h(abase + (uint32_t)(row * (LDA_H * 2) + c * 16), Asrc + (size_t)row * K + c * 8);
            cp16h(bbase + (uint32_t)(row * (LDA_H * 2) + c * 16), Bsrc + (size_t)row * K + c * 8);
        }
        asm volatile("cp.async.commit_group;");
    };

    load_stage(0, 0);
    load_stage(1, 1);

    for (int kt = 0; kt < KT; kt++) {
        asm volatile("cp.async.wait_group 1;");
        __syncthreads();

        if (kt + 2 < KT) load_stage((kt + 2) % TSTAGES, kt + 2);
        else             asm volatile("cp.async.commit_group;");

        const int st = kt % TSTAGES;
        const uint32_t a_u = sbase + (uint32_t)(st * STAGE_B) + a_lm_off;
        const char* bs = smem + st * STAGE_B + TILE_H * 2;

#pragma unroll
        for (int kk = 0; kk < 2; kk++) {
            uint32_t af[4][4], bf[4][2];
#pragma unroll
            for (int i = 0; i < 4; i++)
                ldsm_x4(af[i], a_u + (uint32_t)(i * 16 * LDA_H * 2 + kk * 32));
#pragma unroll
            for (int j = 0; j < 4; j++) {
                int n = wn + 8 * j + g;
                const char* brow = bs + n * (LDA_H * 2) + kk * 32;
                bf[j][0] = *(const uint32_t*)(brow + 4 * tig);
                bf[j][1] = *(const uint32_t*)(brow + 4 * tig + 16);
            }
#pragma unroll
            for (int i = 0; i < 4; i++)
#pragma unroll
                for (int j = 0; j < 4; j++)
                    mma_f16(acc[i][j], af[i], bf[j]);
        }
    }

#pragma unroll
    for (int i = 0; i < 4; i++) {
        int r0 = bm * TBM + wm + 16 * i + g;
#pragma unroll
        for (int j = 0; j < 4; j++) {
            int cn = bn * TBN + wn + 8 * j + 2 * tig;
            if (cn < N) {
                *(float2*)(C + (size_t)r0 * N + cn)       = make_float2(acc[i][j][0], acc[i][j][1]);
                *(float2*)(C + (size_t)(r0 + 8) * N + cn) = make_float2(acc[i][j][2], acc[i][j][3]);
            }
        }
    }
}

static inline void launch_gemm(const __half* A, const __half* BTm, float* C,
                               int M, int N, int K, cudaStream_t st)
{
    int num_bm = M / TBM;
    int num_bn = (N + TBN - 1) / TBN;
    gemm_f16_kernel<<<num_bm * num_bn, 256, GEMM_SMEM, st>>>(A, BTm, C, M, N, K);
}

// ---------------------------------------------------------------------------
// fp32 -> fp16 elementwise
// ---------------------------------------------------------------------------
__global__ void cvt_f16_kernel(const float* __restrict__ src,
                               __half* __restrict__ dst, size_t n4)
{
    size_t i = (size_t)blockIdx.x * blockDim.x + threadIdx.x;
    if (i >= n4) return;
    float4 x = ((const float4*)src)[i];
    __half2* d = (__half2*)dst + 2 * i;
    d[0] = __floats2half2_rn(x.x, x.y);
    d[1] = __floats2half2_rn(x.z, x.w);
}

// Fused pack: [W_qkv | W_b | W_a] -> transposed [QBT_NP, DMODEL] half (zero pad)
__global__ void pack_wqkvbaT_kernel(const float* __restrict__ Wqkv,
                                    const float* __restrict__ Wb,
                                    const float* __restrict__ Wa,
                                    __half* __restrict__ Wt)
{
    __shared__ float t[32][33];
    int nx = blockIdx.x * 32;
    int ky = blockIdx.y * 32;
    int tx = threadIdx.x, ty = threadIdx.y;
#pragma unroll
    for (int i = 0; i < 32; i += 8) {
        int n = nx + tx, k = ky + ty + i;
        float v;
        if      (n < B2_OFF) v = Wqkv[(size_t)k * CONVDIM + n];
        else if (n < A2_OFF) v = Wb[k * 32 + (n - B2_OFF)];
        else if (n < QB_N)   v = Wa[k * 32 + (n - A2_OFF)];
        else                 v = 0.f;
        t[ty + i][tx] = v;
    }
    __syncthreads();
#pragma unroll
    for (int i = 0; i < 32; i += 8) {
        int n = nx + ty + i, k = ky + tx;
        Wt[(size_t)n * DMODEL + k] = __float2half_rn(t[tx][ty + i]);
    }
}

// generic transpose+cvt: src[R][C] fp32 -> dst[C][R] half
__global__ void packT_f16_kernel(const float* __restrict__ src,
                                 __half* __restrict__ dst, int R, int C)
{
    __shared__ float t[32][33];
    int cx = blockIdx.x * 32;
    int ry = blockIdx.y * 32;
    int tx = threadIdx.x, ty = threadIdx.y;
#pragma unroll
    for (int i = 0; i < 32; i += 8)
        t[ty + i][tx] = src[(size_t)(ry + ty + i) * C + cx + tx];
    __syncthreads();
#pragma unroll
    for (int i = 0; i < 32; i += 8)
        dst[(size_t)(cx + ty + i) * R + ry + tx] = __float2half_rn(t[tx][ty + i]);
}

// ---------------------------------------------------------------------------
// Causal depthwise conv (KC=4) + SiLU + split, chunked over rows.
// ---------------------------------------------------------------------------
__global__ void conv_silu_split_kernel(const float* __restrict__ proj,
                                       const float* __restrict__ conv_w,
                                       float* __restrict__ q,
                                       float* __restrict__ k,
                                       float* __restrict__ v,
                                       long row0, int t0, int nrows)
{
    size_t idx = (size_t)blockIdx.x * blockDim.x + threadIdx.x;
    if (idx >= (size_t)nrows * CONVDIM) return;
    int c = (int)(idx & (CONVDIM - 1));
    int r = (int)(idx >> 13);
    size_t bt = (size_t)row0 + r;
    int t = t0 + r;

    float4 w = *(const float4*)(conv_w + (size_t)c * 4);
    const float* base = proj + c;
    float x0 = (t >= 3) ? base[(bt - 3) * QB_N] : 0.f;
    float x1 = (t >= 2) ? base[(bt - 2) * QB_N] : 0.f;
    float x2 = (t >= 1) ? base[(bt - 1) * QB_N] : 0.f;
    float x3 = base[bt * QB_N];

    float acc = x0 * w.x + x1 * w.y + x2 * w.z + x3 * w.w;
    float s = acc / (1.f + expf(-acc));

    if (c < KEYDIM)           q[bt * KEYDIM + c] = s;
    else if (c < 2 * KEYDIM)  k[bt * KEYDIM + (c - KEYDIM)] = s;
    else                      v[bt * VALDIM + (c - 2 * KEYDIM)] = s;
}

// ---------------------------------------------------------------------------
// L2 norm over DK=128 (one warp per row); q gets extra DK^-0.5 (chunked)
// ---------------------------------------------------------------------------
__global__ void l2norm_qk_kernel(float* __restrict__ q, float* __restrict__ k,
                                 int nrows)
{
    int wg   = (blockIdx.x * blockDim.x + threadIdx.x) >> 5;
    int lane = threadIdx.x & 31;
    if (wg >= 2 * nrows) return;

    float* base;
    float extra;
    if (wg < nrows) { base = q + (size_t)wg * DK; extra = 0.08838834764831845f; }
    else            { base = k + (size_t)(wg - nrows) * DK; extra = 1.f; }

    float4 x = ((float4*)base)[lane];
    float ss = x.x*x.x + x.y*x.y + x.z*x.z + x.w*x.w;
#pragma unroll
    for (int off = 16; off > 0; off >>= 1)
        ss += __shfl_xor_sync(0xffffffffu, ss, off);
    float inv = rsqrtf(ss + 1e-6f) * extra;
    x.x *= inv; x.y *= inv; x.z *= inv; x.w *= inv;
    ((float4*)base)[lane] = x;
}

// ---------------------------------------------------------------------------
// beta/decay (chunked)
// ---------------------------------------------------------------------------
__global__ void beta_decay_kernel(const float* __restrict__ proj,
                                  const float* __restrict__ dt_bias,
                                  const float* __restrict__ A_log,
                                  float* __restrict__ beta,
                                  float* __restrict__ decay,
                                  long row0, int nrows)
{
    int idx = blockIdx.x * blockDim.x + threadIdx.x;
    if (idx >= nrows * NVH) return;
    int h = idx & (NVH - 1);
    size_t bt = (size_t)row0 + (idx >> 5);
    float b = proj[bt * QB_N + B2_OFF + h];
    beta[bt * NVH + h] = 1.f / (1.f + expf(-b));
    float a = proj[bt * QB_N + A2_OFF + h] + dt_bias[h];
    float sp = (a > 20.f) ? a : log1pf(expf(a));
    decay[bt * NVH + h] = expf(-expf(A_log[h]) * sp);
}

// ---------------------------------------------------------------------------
// Gated delta rule scan — chunked, state in packed f32x2 registers.
// ---------------------------------------------------------------------------
__global__ void __launch_bounds__(128) scan_kernel(
    const float* __restrict__ qn, const float* __restrict__ kn,
    const float* __restrict__ v,  const float* __restrict__ decay,
    const float* __restrict__ beta, float* __restrict__ o,
    float* __restrict__ Sst, int t0, int t1)
{
    const int blk = blockIdx.x;
    const int b   = blk >> 6;
    const int rem = blk & 63;
    const int h   = rem >> 1;
    const int seg = rem & 1;
    const int h2  = h >> 1;
    const int tid = threadIdx.x;
    const int col  = tid >> 1;
    const int half = tid & 1;
    const int gcol = seg * 64 + col;
    const int koff = half * 64;

    __shared__ float sq[128];
    __shared__ float sk[128];

    float* Sg = Sst + (size_t)blk * (64 * 128);

    unsigned long long S2[32];
    if (t0 == 0) {
#pragma unroll
        for (int j = 0; j < 32; j++) S2[j] = 0ULL;
    } else {
#pragma unroll
        for (int j = 0; j < 32; j++)
            S2[j] = pack2(Sg[(2*j) * 128 + tid], Sg[(2*j+1) * 128 + tid]);
    }

    const size_t bt0 = (size_t)b * TLEN;

    float pq = qn[((bt0 + t0)*NKH + h2) * DK + tid];
    float pk = kn[((bt0 + t0)*NKH + h2) * DK + tid];
    float pv = v [((bt0 + t0)*NVH + h ) * DV + gcol];
    float pd = decay[(bt0 + t0) * NVH + h];
    float pb = beta [(bt0 + t0) * NVH + h];

    for (int t = t0; t < t1; t++) {
        __syncthreads();
        sq[tid] = pq;
        sk[tid] = pk;
        float cv = pv, cd = pd, cb = pb;
        __syncthreads();

        if (t + 1 < t1) {
            size_t bt = bt0 + t + 1;
            pq = qn[(bt*NKH + h2) * DK + tid];
            pk = kn[(bt*NKH + h2) * DK + tid];
            pv = v [(bt*NVH + h ) * DV + gcol];
            pd = decay[bt * NVH + h];
            pb = beta [bt * NVH + h];
        }

        const unsigned long long cd2 = pack2(cd, cd);
        const unsigned long long* sk2 = (const unsigned long long*)(sk + koff);
        const unsigned long long* sq2 = (const unsigned long long*)(sq + koff);

        unsigned long long skr[32];
        unsigned long long a0 = 0ULL, a1 = 0ULL, a2 = 0ULL, a3 = 0ULL;
#pragma unroll
        for (int j = 0; j < 32; j += 4) {
            skr[j+0] = sk2[j+0]; S2[j+0] = mul2(S2[j+0], cd2); a0 = fma2(skr[j+0], S2[j+0], a0);
            skr[j+1] = sk2[j+1]; S2[j+1] = mul2(S2[j+1], cd2); a1 = fma2(skr[j+1], S2[j+1], a1);
            skr[j+2] = sk2[j+2]; S2[j+2] = mul2(S2[j+2], cd2); a2 = fma2(skr[j+2], S2[j+2], a2);
            skr[j+3] = sk2[j+3]; S2[j+3] = mul2(S2[j+3], cd2); a3 = fma2(skr[j+3], S2[j+3], a3);
        }
        float x0, y0, x1, y1, x2, y2, x3, y3;
        unpack2(a0, x0, y0); unpack2(a1, x1, y1);
        unpack2(a2, x2, y2); unpack2(a3, x3, y3);
        float kS = ((x0 + y0) + (x1 + y1)) + ((x2 + y2) + (x3 + y3));
        kS += __shfl_xor_sync(0xffffffffu, kS, 1);

        float upd = cb * (cv - kS);
        const unsigned long long upd2 = pack2(upd, upd);

        unsigned long long o0 = 0ULL, o1 = 0ULL, o2 = 0ULL, o3 = 0ULL;
#pragma unroll
        for (int j = 0; j < 32; j += 4) {
            S2[j+0] = fma2(skr[j+0], upd2, S2[j+0]); o0 = fma2(sq2[j+0], S2[j+0], o0);
            S2[j+1] = fma2(skr[j+1], upd2, S2[j+1]); o1 = fma2(sq2[j+1], S2[j+1], o1);
            S2[j+2] = fma2(skr[j+2], upd2, S2[j+2]); o2 = fma2(sq2[j+2], S2[j+2], o2);
            S2[j+3] = fma2(skr[j+3], upd2, S2[j+3]); o3 = fma2(sq2[j+3], S2[j+3], o3);
        }
        unpack2(o0, x0, y0); unpack2(o1, x1, y1);
        unpack2(o2, x2, y2); unpack2(o3, x3, y3);
        float oa = ((x0 + y0) + (x1 + y1)) + ((x2 + y2) + (x3 + y3));
        oa += __shfl_xor_sync(0xffffffffu, oa, 1);
        if (!half)
            o[((bt0 + t)*NVH + h) * DV + gcol] = oa;
    }

    if (t1 < TLEN) {
#pragma unroll
        for (int j = 0; j < 32; j++) {
            float lo, hi;
            unpack2(S2[j], lo, hi);
            Sg[(2*j)   * 128 + tid] = lo;
            Sg[(2*j+1) * 128 + tid] = hi;
        }
    }
}

// ---------------------------------------------------------------------------
// Gated RMSNorm over nrows rows (pointers pre-offset); emits half
// ---------------------------------------------------------------------------
__global__ void gate_kernel(const float* __restrict__ o, const float* __restrict__ z,
                            const float* __restrict__ norm_w, __half* __restrict__ oh,
                            int nrows)
{
    int wg   = (blockIdx.x * blockDim.x + threadIdx.x) >> 5;
    int lane = threadIdx.x & 31;
    if (wg >= nrows) return;

    float4 x = ((const float4*)(o + (size_t)wg * DV))[lane];
    float ss = x.x*x.x + x.y*x.y + x.z*x.z + x.w*x.w;
#pragma unroll
    for (int off = 16; off > 0; off >>= 1)
        ss += __shfl_xor_sync(0xffffffffu, ss, off);
    float r = rsqrtf(ss * (1.f / DV) + 1e-6f);

    float4 zv = ((const float4*)(z + (size_t)wg * DV))[lane];
    float4 nw = ((const float4*)norm_w)[lane];

    float s0 = zv.x / (1.f + expf(-zv.x));
    float s1 = zv.y / (1.f + expf(-zv.y));
    float s2 = zv.z / (1.f + expf(-zv.z));
    float s3 = zv.w / (1.f + expf(-zv.w));

    __half2* dst = (__half2*)(oh + (size_t)wg * DV) + 2 * lane;
    dst[0] = __floats2half2_rn(x.x * r * nw.x * s0, x.y * r * nw.y * s1);
    dst[1] = __floats2half2_rn(x.z * r * nw.z * s2, x.w * r * nw.w * s3);
}

// ---------------------------------------------------------------------------
// Launch: fully chunked pipeline with capture-clean fork/join.
// ---------------------------------------------------------------------------
extern "C" void kernel_launch(void* const* d_in, const int* in_sizes, int n_in,
                              void* d_out, int out_size)
{
    const float* hs      = (const float*)d_in[0];
    const float* W_qkv   = (const float*)d_in[1];
    const float* W_z     = (const float*)d_in[2];
    const float* W_b     = (const float*)d_in[3];
    const float* W_a     = (const float*)d_in[4];
    const float* conv_w  = (const float*)d_in[5];
    const float* dt_bias = (const float*)d_in[6];
    const float* A_log   = (const float*)d_in[7];
    const float* norm_w  = (const float*)d_in[8];
    const float* W_out   = (const float*)d_in[9];
    float* out = (float*)d_out;

    float *qkvba, *z, *q, *k, *v, *beta, *decay, *o, *Sst;
    __half *hs_h, *wqkvbaT, *wzT, *woutT, *oh;
    cudaGetSymbolAddress((void**)&qkvba,   g_qkvba);
    cudaGetSymbolAddress((void**)&z,       g_z);
    cudaGetSymbolAddress((void**)&q,       g_q);
    cudaGetSymbolAddress((void**)&k,       g_k);
    cudaGetSymbolAddress((void**)&v,       g_v);
    cudaGetSymbolAddress((void**)&beta,    g_beta);
    cudaGetSymbolAddress((void**)&decay,   g_decay);
    cudaGetSymbolAddress((void**)&o,       g_o);
    cudaGetSymbolAddress((void**)&Sst,     g_S);
    cudaGetSymbolAddress((void**)&hs_h,    g_hs_h);
    cudaGetSymbolAddress((void**)&wqkvbaT, g_wqkvbaT);
    cudaGetSymbolAddress((void**)&wzT,     g_wzT);
    cudaGetSymbolAddress((void**)&woutT,   g_woutT);
    cudaGetSymbolAddress((void**)&oh,      g_oh);

    static cudaStream_t s1 = nullptr, s2 = nullptr;
    static cudaEvent_t ev_root = nullptr, ev_in = nullptr, ev_wz = nullptr;
    static cudaEvent_t ev_feed[NCHUNK] = {}, ev_scan[NCHUNK] = {}, ev_z[NCHUNK] = {};
    static cudaEvent_t ev_done = nullptr, ev_s1done = nullptr;
    static bool init_done = false;
    if (!init_done) {
        cudaStreamCreateWithFlags(&s1, cudaStreamNonBlocking);
        cudaStreamCreateWithFlags(&s2, cudaStreamNonBlocking);
        cudaEventCreateWithFlags(&ev_root, cudaEventDisableTiming);
        cudaEventCreateWithFlags(&ev_in,   cudaEventDisableTiming);
        cudaEventCreateWithFlags(&ev_wz,   cudaEventDisableTiming);
        for (int c = 0; c < NCHUNK; c++) {
            cudaEventCreateWithFlags(&ev_feed[c], cudaEventDisableTiming);
            cudaEventCreateWithFlags(&ev_scan[c], cudaEventDisableTiming);
            cudaEventCreateWithFlags(&ev_z[c],    cudaEventDisableTiming);
        }
        cudaEventCreateWithFlags(&ev_done,   cudaEventDisableTiming);
        cudaEventCreateWithFlags(&ev_s1done, cudaEventDisableTiming);
        cudaFuncSetAttribute(gemm_f16_kernel,
                             cudaFuncAttributeMaxDynamicSharedMemorySize, GEMM_SMEM);
        init_done = true;
    }

    const cudaStream_t s0 = 0;
    dim3 tb32(32, 8);

    // ---- capture-clean fork: side streams join the graph FIRST ----
    cudaEventRecord(ev_root, s0);
    cudaStreamWaitEvent(s1, ev_root, 0);
    cudaStreamWaitEvent(s2, ev_root, 0);

    // ---- s2: wz / wout weight packs ----
    {
        dim3 gz(VALDIM / 32, DMODEL / 32);
        packT_f16_kernel<<<gz, tb32, 0, s2>>>(W_z, wzT, DMODEL, VALDIM);
        cudaEventRecord(ev_wz, s2);
        dim3 go(DMODEL / 32, VALDIM / 32);
        packT_f16_kernel<<<go, tb32, 0, s2>>>(W_out, woutT, VALDIM, DMODEL);
    }

    // ---- s0: input prepasses ----
    {
        size_t n4 = (size_t)BT * DMODEL / 4;
        cvt_f16_kernel<<<(unsigned)((n4 + 255) / 256), 256, 0, s0>>>(hs, hs_h, n4);
        dim3 gq(QBT_NP / 32, DMODEL / 32);
        pack_wqkvbaT_kernel<<<gq, tb32, 0, s0>>>(W_qkv, W_b, W_a, wqkvbaT);
        cudaEventRecord(ev_in, s0);
    }

    // ---- s1: chunked feed pipeline (+ z chunk each iteration) ----
    cudaStreamWaitEvent(s1, ev_in, 0);
    cudaStreamWaitEvent(s1, ev_wz, 0);
    for (int c = 0; c < NCHUNK; c++) {
        const int t0 = c * TC;
        for (int b = 0; b < BATCH; b++) {
            const long row0 = (long)b * TLEN + t0;
            launch_gemm(hs_h + (size_t)row0 * DMODEL, wqkvbaT,
                        qkvba + (size_t)row0 * QB_N, TC, QB_N, DMODEL, s1);
        }
        for (int b = 0; b < BATCH; b++) {
            const long row0 = (long)b * TLEN + t0;
            size_t n = (size_t)TC * CONVDIM;
            conv_silu_split_kernel<<<(unsigned)((n + 255) / 256), 256, 0, s1>>>(
                qkvba, conv_w, q, k, v, row0, t0, TC);
        }
        for (int b = 0; b < BATCH; b++) {
            const long row0 = (long)b * TLEN + t0;
            int hr = TC * NKH;
            l2norm_qk_kernel<<<(2 * hr + 7) / 8, 256, 0, s1>>>(
                q + (size_t)row0 * KEYDIM, k + (size_t)row0 * KEYDIM, hr);
        }
        for (int b = 0; b < BATCH; b++) {
            const long row0 = (long)b * TLEN + t0;
            beta_decay_kernel<<<(TC * NVH + 255) / 256, 256, 0, s1>>>(
                qkvba, dt_bias, A_log, beta, decay, row0, TC);
        }
        cudaEventRecord(ev_feed[c], s1);

        for (int b = 0; b < BATCH; b++) {
            const long row0 = (long)b * TLEN + t0;
            launch_gemm(hs_h + (size_t)row0 * DMODEL, wzT,
                        z + (size_t)row0 * VALDIM, TC, VALDIM, DMODEL, s1);
        }
        cudaEventRecord(ev_z[c], s1);
    }
    cudaEventRecord(ev_s1done, s1);

    // ---- s0: scan chunks ----
    for (int c = 0; c < NCHUNK; c++) {
        cudaStreamWaitEvent(s0, ev_feed[c], 0);
        scan_kernel<<<BATCH * NVH * 2, 128, 0, s0>>>(
            q, k, v, decay, beta, o, Sst, c * TC, (c + 1) * TC);
        cudaEventRecord(ev_scan[c], s0);
    }

    // ---- s2: gate + out-projection per chunk ----
    for (int c = 0; c < NCHUNK; c++) {
        cudaStreamWaitEvent(s2, ev_scan[c], 0);
        cudaStreamWaitEvent(s2, ev_z[c], 0);
        for (int b = 0; b < BATCH; b++) {
            const size_t row0 = (size_t)b * TLEN + c * TC;
            const int rows = TC * NVH;
            gate_kernel<<<(rows + 7) / 8, 256, 0, s2>>>(
                o + row0 * VALDIM, z + row0 * VALDIM, norm_w, oh + row0 * VALDIM, rows);
            launch_gemm(oh + row0 * VALDIM, woutT, out + row0 * DMODEL,
                        TC, DMODEL, VALDIM, s2);
        }
    }

    // ---- join everything back to s0 ----
    cudaEventRecord(ev_done, s2);
    cudaStreamWaitEvent(s0, ev_done, 0);
    cudaStreamWaitEvent(s0, ev_s1done, 0);
}

// round 16
// speedup vs baseline: 1.0408x; 1.0408x over previous
#include <cuda_runtime.h>
#include <cuda_fp16.h>
#include <math.h>
#include <stdint.h>

// ---------------------------------------------------------------------------
// Problem constants (Qwen3.5 GatedDeltaNet): B=2, T=4096, D=2048
// ---------------------------------------------------------------------------
#define BATCH   2
#define TLEN    4096
#define BT      8192
#define DMODEL  2048
#define NVH     32
#define NKH     16
#define DK      128
#define DV      128
#define KEYDIM  (NKH*DK)                 // 2048
#define VALDIM  (NVH*DV)                 // 4096
#define CONVDIM (2*KEYDIM + VALDIM)      // 8192
#define QB_N    (CONVDIM + 64)           // 8256 : [qkv | b | a]
#define QBT_NP  8320                     // padded for B tiles
#define B2_OFF  CONVDIM
#define A2_OFF  (CONVDIM + 32)
#define NCHUNK  4
#define TC      (TLEN/NCHUNK)            // 1024 t-steps per chunk

// ---------------------------------------------------------------------------
// Scratch (static device globals)
// ---------------------------------------------------------------------------
__device__ float  g_qkvba[(size_t)BT * QB_N];
__device__ float  g_z[(size_t)BT * VALDIM];
__device__ float  g_q[(size_t)BT * KEYDIM];
__device__ float  g_k[(size_t)BT * KEYDIM];
__device__ float  g_v[(size_t)BT * VALDIM];
__device__ float  g_beta[BT * NVH];
__device__ float  g_decay[BT * NVH];
__device__ float  g_o[(size_t)BT * VALDIM];
__device__ float  g_S[(size_t)128 * 64 * 128];          // scan state checkpoints
// half-precision GEMM operands
__device__ __half g_hs_h[(size_t)BT * DMODEL];
__device__ __half g_wqkvbaT[(size_t)QBT_NP * DMODEL];   // [N,K]
__device__ __half g_wzT[(size_t)VALDIM * DMODEL];       // [N,K]
__device__ __half g_woutT[(size_t)DMODEL * VALDIM];     // [N,K]
__device__ __half g_oh[(size_t)BT * VALDIM];            // gated o, half

// ---------------------------------------------------------------------------
// FP16 tensor-core GEMM (mma.sync m16n8k16, fp32 accum), batched over grid.y.
// C[y][M,N] = A[y][M,K] @ BT[N,K]^T with per-batch element strides.
// ---------------------------------------------------------------------------
#define TSTAGES 3
#define TBM 128
#define TBN 128
#define TBK 32
#define LDA_H 40
#define TILE_H (128*LDA_H)
#define STAGE_B (2*TILE_H*2)
#define GEMM_SMEM (TSTAGES*STAGE_B)
#define GROUP_M 8

__device__ __forceinline__ void cp16h(uint32_t dst, const __half* src) {
    asm volatile("cp.async.cg.shared.global [%0], [%1], 16;" :: "r"(dst), "l"(src));
}

__device__ __forceinline__ void ldsm_x4(uint32_t* r, uint32_t addr) {
    asm volatile("ldmatrix.sync.aligned.m8n8.x4.shared.b16 {%0,%1,%2,%3}, [%4];"
        : "=r"(r[0]), "=r"(r[1]), "=r"(r[2]), "=r"(r[3]) : "r"(addr));
}

__device__ __forceinline__ void mma_f16(float* c, const uint32_t* a, const uint32_t* b) {
    asm volatile(
        "mma.sync.aligned.m16n8k16.row.col.f32.f16.f16.f32 "
        "{%0,%1,%2,%3}, {%4,%5,%6,%7}, {%8,%9}, {%0,%1,%2,%3};"
        : "+f"(c[0]), "+f"(c[1]), "+f"(c[2]), "+f"(c[3])
        : "r"(a[0]), "r"(a[1]), "r"(a[2]), "r"(a[3]), "r"(b[0]), "r"(b[1]));
}

__global__ __launch_bounds__(256, 2) void gemm_f16_kernel(
    const __half* __restrict__ Ab, const __half* __restrict__ BTm,
    float* __restrict__ Cb, int M, int N, int K,
    long strideA, long strideC)
{
    extern __shared__ char smem[];
    const uint32_t sbase = (uint32_t)__cvta_generic_to_shared(smem);

    const __half* A = Ab + (size_t)blockIdx.y * strideA;
    float*        C = Cb + (size_t)blockIdx.y * strideC;

    const int num_bm = M / TBM;
    const int num_bn = (N + TBN - 1) / TBN;
    const int pid    = blockIdx.x;
    const int ppg    = GROUP_M * num_bn;
    const int gid    = pid / ppg;
    const int fbm    = gid * GROUP_M;
    const int gsz    = min(GROUP_M, num_bm - fbm);
    const int bm     = fbm + (pid % ppg) % gsz;
    const int bn     = (pid % ppg) / gsz;

    const int tid  = threadIdx.x;
    const int warp = tid >> 5;
    const int lane = tid & 31;
    const int g    = lane >> 2;
    const int tig  = lane & 3;
    const int wm   = (warp >> 2) * 64;
    const int wn   = (warp & 3) * 32;

    float acc[4][4][4];
#pragma unroll
    for (int i = 0; i < 4; i++)
#pragma unroll
        for (int j = 0; j < 4; j++)
#pragma unroll
            for (int r = 0; r < 4; r++) acc[i][j][r] = 0.f;

    const int KT = K / TBK;

    const uint32_t a_lm_off =
        (uint32_t)(((wm + (lane & 7) + 8 * ((lane >> 3) & 1)) * LDA_H + (lane >> 4) * 8) * 2);

    auto load_stage = [&](int s, int kt) {
        uint32_t abase = sbase + (uint32_t)(s * STAGE_B);
        uint32_t bbase = abase + (uint32_t)(TILE_H * 2);
        const __half* Asrc = A   + (size_t)(bm * TBM) * K + kt * TBK;
        const __half* Bsrc = BTm + (size_t)(bn * TBN) * K + kt * TBK;
#pragma unroll
        for (int h = 0; h < 2; h++) {
            int id  = tid + h * 256;
            int row = id >> 2, c = id & 3;
            cp16h(abase + (uint32_t)(row * (LDA_H * 2) + c * 16), Asrc + (size_t)row * K + c * 8);
            cp16h(bbase + (uint32_t)(row * (LDA_H * 2) + c * 16), Bsrc + (size_t)row * K + c * 8);
        }
        asm volatile("cp.async.commit_group;");
    };

    load_stage(0, 0);
    load_stage(1, 1);

    for (int kt = 0; kt < KT; kt++) {
        asm volatile("cp.async.wait_group 1;");
        __syncthreads();

        if (kt + 2 < KT) load_stage((kt + 2) % TSTAGES, kt + 2);
        else             asm volatile("cp.async.commit_group;");

        const int st = kt % TSTAGES;
        const uint32_t a_u = sbase + (uint32_t)(st * STAGE_B) + a_lm_off;
        const char* bs = smem + st * STAGE_B + TILE_H * 2;

#pragma unroll
        for (int kk = 0; kk < 2; kk++) {
            uint32_t af[4][4], bf[4][2];
#pragma unroll
            for (int i = 0; i < 4; i++)
                ldsm_x4(af[i], a_u + (uint32_t)(i * 16 * LDA_H * 2 + kk * 32));
#pragma unroll
            for (int j = 0; j < 4; j++) {
                int n = wn + 8 * j + g;
                const char* brow = bs + n * (LDA_H * 2) + kk * 32;
                bf[j][0] = *(const uint32_t*)(brow + 4 * tig);
                bf[j][1] = *(const uint32_t*)(brow + 4 * tig + 16);
            }
#pragma unroll
            for (int i = 0; i < 4; i++)
#pragma unroll
                for (int j = 0; j < 4; j++)
                    mma_f16(acc[i][j], af[i], bf[j]);
        }
    }

#pragma unroll
    for (int i = 0; i < 4; i++) {
        int r0 = bm * TBM + wm + 16 * i + g;
#pragma unroll
        for (int j = 0; j < 4; j++) {
            int cn = bn * TBN + wn + 8 * j + 2 * tig;
            if (cn < N) {
                *(float2*)(C + (size_t)r0 * N + cn)       = make_float2(acc[i][j][0], acc[i][j][1]);
                *(float2*)(C + (size_t)(r0 + 8) * N + cn) = make_float2(acc[i][j][2], acc[i][j][3]);
            }
        }
    }
}

static inline void launch_gemm_b(const __half* A, const __half* BTm, float* C,
                                 int M, int N, int K,
                                 long strideA, long strideC, int nbatch,
                                 cudaStream_t st)
{
    int num_bm = M / TBM;
    int num_bn = (N + TBN - 1) / TBN;
    dim3 grid(num_bm * num_bn, nbatch);
    gemm_f16_kernel<<<grid, 256, GEMM_SMEM, st>>>(A, BTm, C, M, N, K, strideA, strideC);
}

// ---------------------------------------------------------------------------
// fp32 -> fp16 elementwise
// ---------------------------------------------------------------------------
__global__ void cvt_f16_kernel(const float* __restrict__ src,
                               __half* __restrict__ dst, size_t n4)
{
    size_t i = (size_t)blockIdx.x * blockDim.x + threadIdx.x;
    if (i >= n4) return;
    float4 x = ((const float4*)src)[i];
    __half2* d = (__half2*)dst + 2 * i;
    d[0] = __floats2half2_rn(x.x, x.y);
    d[1] = __floats2half2_rn(x.z, x.w);
}

// Fused pack: [W_qkv | W_b | W_a] -> transposed [QBT_NP, DMODEL] half (zero pad)
__global__ void pack_wqkvbaT_kernel(const float* __restrict__ Wqkv,
                                    const float* __restrict__ Wb,
                                    const float* __restrict__ Wa,
                                    __half* __restrict__ Wt)
{
    __shared__ float t[32][33];
    int nx = blockIdx.x * 32;
    int ky = blockIdx.y * 32;
    int tx = threadIdx.x, ty = threadIdx.y;
#pragma unroll
    for (int i = 0; i < 32; i += 8) {
        int n = nx + tx, k = ky + ty + i;
        float v;
        if      (n < B2_OFF) v = Wqkv[(size_t)k * CONVDIM + n];
        else if (n < A2_OFF) v = Wb[k * 32 + (n - B2_OFF)];
        else if (n < QB_N)   v = Wa[k * 32 + (n - A2_OFF)];
        else                 v = 0.f;
        t[ty + i][tx] = v;
    }
    __syncthreads();
#pragma unroll
    for (int i = 0; i < 32; i += 8) {
        int n = nx + ty + i, k = ky + tx;
        Wt[(size_t)n * DMODEL + k] = __float2half_rn(t[tx][ty + i]);
    }
}

// generic transpose+cvt: src[R][C] fp32 -> dst[C][R] half
__global__ void packT_f16_kernel(const float* __restrict__ src,
                                 __half* __restrict__ dst, int R, int C)
{
    __shared__ float t[32][33];
    int cx = blockIdx.x * 32;
    int ry = blockIdx.y * 32;
    int tx = threadIdx.x, ty = threadIdx.y;
#pragma unroll
    for (int i = 0; i < 32; i += 8)
        t[ty + i][tx] = src[(size_t)(ry + ty + i) * C + cx + tx];
    __syncthreads();
#pragma unroll
    for (int i = 0; i < 32; i += 8)
        dst[(size_t)(cx + ty + i) * R + ry + tx] = __float2half_rn(t[tx][ty + i]);
}

// ---------------------------------------------------------------------------
// Causal depthwise conv (KC=4) + SiLU + split; covers BOTH batches of chunk.
// Rows r in [0, 2*TC): batch = r/TC, tt = r%TC, bt = batch*TLEN + t0 + tt.
// ---------------------------------------------------------------------------
__global__ void conv_silu_split_kernel(const float* __restrict__ proj,
                                       const float* __restrict__ conv_w,
                                       float* __restrict__ q,
                                       float* __restrict__ k,
                                       float* __restrict__ v,
                                       int t0)
{
    size_t idx = (size_t)blockIdx.x * blockDim.x + threadIdx.x;
    if (idx >= (size_t)(BATCH * TC) * CONVDIM) return;
    int c = (int)(idx & (CONVDIM - 1));
    int r = (int)(idx >> 13);
    int bsel = r / TC;
    int tt   = r - bsel * TC;
    size_t bt = (size_t)bsel * TLEN + t0 + tt;
    int t = t0 + tt;

    float4 w = *(const float4*)(conv_w + (size_t)c * 4);
    const float* base = proj + c;
    float x0 = (t >= 3) ? base[(bt - 3) * QB_N] : 0.f;
    float x1 = (t >= 2) ? base[(bt - 2) * QB_N] : 0.f;
    float x2 = (t >= 1) ? base[(bt - 1) * QB_N] : 0.f;
    float x3 = base[bt * QB_N];

    float acc = x0 * w.x + x1 * w.y + x2 * w.z + x3 * w.w;
    float s = acc / (1.f + expf(-acc));

    if (c < KEYDIM)           q[bt * KEYDIM + c] = s;
    else if (c < 2 * KEYDIM)  k[bt * KEYDIM + (c - KEYDIM)] = s;
    else                      v[bt * VALDIM + (c - 2 * KEYDIM)] = s;
}

// ---------------------------------------------------------------------------
// L2 norm over DK=128 (one warp per head-row); both batches, q and k.
// hr = TC*NKH head-rows per batch per operand.
// ---------------------------------------------------------------------------
__global__ void l2norm_qk_kernel(float* __restrict__ q, float* __restrict__ k,
                                 int t0)
{
    const int hr = TC * NKH;
    int wg   = (blockIdx.x * blockDim.x + threadIdx.x) >> 5;
    int lane = threadIdx.x & 31;
    if (wg >= 4 * hr) return;

    int isK  = wg >= 2 * hr;
    int w2   = wg - isK * 2 * hr;
    int bsel = w2 >= hr;
    int j    = w2 - bsel * hr;
    size_t bt = (size_t)bsel * TLEN + t0 + (j >> 4);   // j / NKH
    int head  = j & (NKH - 1);

    float* base = (isK ? k : q) + (bt * NKH + head) * DK;
    float extra = isK ? 1.f : 0.08838834764831845f;

    float4 x = ((float4*)base)[lane];
    float ss = x.x*x.x + x.y*x.y + x.z*x.z + x.w*x.w;
#pragma unroll
    for (int off = 16; off > 0; off >>= 1)
        ss += __shfl_xor_sync(0xffffffffu, ss, off);
    float inv = rsqrtf(ss + 1e-6f) * extra;
    x.x *= inv; x.y *= inv; x.z *= inv; x.w *= inv;
    ((float4*)base)[lane] = x;
}

// ---------------------------------------------------------------------------
// beta/decay; both batches of one chunk
// ---------------------------------------------------------------------------
__global__ void beta_decay_kernel(const float* __restrict__ proj,
                                  const float* __restrict__ dt_bias,
                                  const float* __restrict__ A_log,
                                  float* __restrict__ beta,
                                  float* __restrict__ decay,
                                  int t0)
{
    int idx = blockIdx.x * blockDim.x + threadIdx.x;
    if (idx >= BATCH * TC * NVH) return;
    int h = idx & (NVH - 1);
    int r = idx >> 5;
    int bsel = r / TC;
    size_t bt = (size_t)bsel * TLEN + t0 + (r - bsel * TC);
    float b = proj[bt * QB_N + B2_OFF + h];
    beta[bt * NVH + h] = 1.f / (1.f + expf(-b));
    float a = proj[bt * QB_N + A2_OFF + h] + dt_bias[h];
    float sp = (a > 20.f) ? a : log1pf(expf(a));
    decay[bt * NVH + h] = expf(-expf(A_log[h]) * sp);
}

// ---------------------------------------------------------------------------
// Gated delta rule scan — chunked over [t0, t1), state checkpointed globally.
// (R14 scalar version — known-good.)
// ---------------------------------------------------------------------------
__global__ void __launch_bounds__(128) scan_kernel(
    const float* __restrict__ qn, const float* __restrict__ kn,
    const float* __restrict__ v,  const float* __restrict__ decay,
    const float* __restrict__ beta, float* __restrict__ o,
    float* __restrict__ Sst, int t0, int t1)
{
    const int blk = blockIdx.x;
    const int b   = blk >> 6;
    const int rem = blk & 63;
    const int h   = rem >> 1;
    const int seg = rem & 1;
    const int h2  = h >> 1;
    const int tid = threadIdx.x;
    const int col  = tid >> 1;
    const int half = tid & 1;
    const int gcol = seg * 64 + col;
    const int koff = half * 64;

    __shared__ float sq[128];
    __shared__ float sk[128];

    float* Sg = Sst + (size_t)blk * (64 * 128);

    float S[64];
    if (t0 == 0) {
#pragma unroll
        for (int i = 0; i < 64; i++) S[i] = 0.f;
    } else {
#pragma unroll
        for (int i = 0; i < 64; i++) S[i] = Sg[i * 128 + tid];
    }

    const size_t bt0 = (size_t)b * TLEN;

    float pq = qn[((bt0 + t0)*NKH + h2) * DK + tid];
    float pk = kn[((bt0 + t0)*NKH + h2) * DK + tid];
    float pv = v [((bt0 + t0)*NVH + h ) * DV + gcol];
    float pd = decay[(bt0 + t0) * NVH + h];
    float pb = beta [(bt0 + t0) * NVH + h];

    for (int t = t0; t < t1; t++) {
        __syncthreads();
        sq[tid] = pq;
        sk[tid] = pk;
        float cv = pv, cd = pd, cb = pb;
        __syncthreads();

        if (t + 1 < t1) {
            size_t bt = bt0 + t + 1;
            pq = qn[(bt*NKH + h2) * DK + tid];
            pk = kn[(bt*NKH + h2) * DK + tid];
            pv = v [(bt*NVH + h ) * DV + gcol];
            pd = decay[bt * NVH + h];
            pb = beta [bt * NVH + h];
        }

        float a0 = 0.f, a1 = 0.f, a2 = 0.f, a3 = 0.f;
#pragma unroll
        for (int i = 0; i < 64; i += 4) {
            S[i+0] *= cd; a0 = fmaf(sk[koff+i+0], S[i+0], a0);
            S[i+1] *= cd; a1 = fmaf(sk[koff+i+1], S[i+1], a1);
            S[i+2] *= cd; a2 = fmaf(sk[koff+i+2], S[i+2], a2);
            S[i+3] *= cd; a3 = fmaf(sk[koff+i+3], S[i+3], a3);
        }
        float kS = (a0 + a1) + (a2 + a3);
        kS += __shfl_xor_sync(0xffffffffu, kS, 1);

        float upd = cb * (cv - kS);

        float o0 = 0.f, o1 = 0.f, o2 = 0.f, o3 = 0.f;
#pragma unroll
        for (int i = 0; i < 64; i += 4) {
            S[i+0] = fmaf(sk[koff+i+0], upd, S[i+0]); o0 = fmaf(sq[koff+i+0], S[i+0], o0);
            S[i+1] = fmaf(sk[koff+i+1], upd, S[i+1]); o1 = fmaf(sq[koff+i+1], S[i+1], o1);
            S[i+2] = fmaf(sk[koff+i+2], upd, S[i+2]); o2 = fmaf(sq[koff+i+2], S[i+2], o2);
            S[i+3] = fmaf(sk[koff+i+3], upd, S[i+3]); o3 = fmaf(sq[koff+i+3], S[i+3], o3);
        }
        float oa = (o0 + o1) + (o2 + o3);
        oa += __shfl_xor_sync(0xffffffffu, oa, 1);
        if (!half)
            o[((bt0 + t)*NVH + h) * DV + gcol] = oa;
    }

    if (t1 < TLEN) {
#pragma unroll
        for (int i = 0; i < 64; i++) Sg[i * 128 + tid] = S[i];
    }
}

// ---------------------------------------------------------------------------
// Gated RMSNorm; both batches of one chunk; emits half
// ---------------------------------------------------------------------------
__global__ void gate_kernel(const float* __restrict__ o, const float* __restrict__ z,
                            const float* __restrict__ norm_w, __half* __restrict__ oh,
                            int t0)
{
    const int rows_pb = TC * NVH;
    int wg   = (blockIdx.x * blockDim.x + threadIdx.x) >> 5;
    int lane = threadIdx.x & 31;
    if (wg >= BATCH * rows_pb) return;

    int bsel = wg / rows_pb;
    int j    = wg - bsel * rows_pb;
    size_t row = ((size_t)bsel * TLEN + t0) * NVH + j;

    float4 x = ((const float4*)(o + row * DV))[lane];
    float ss = x.x*x.x + x.y*x.y + x.z*x.z + x.w*x.w;
#pragma unroll
    for (int off = 16; off > 0; off >>= 1)
        ss += __shfl_xor_sync(0xffffffffu, ss, off);
    float r = rsqrtf(ss * (1.f / DV) + 1e-6f);

    float4 zv = ((const float4*)(z + row * DV))[lane];
    float4 nw = ((const float4*)norm_w)[lane];

    float s0 = zv.x / (1.f + expf(-zv.x));
    float s1 = zv.y / (1.f + expf(-zv.y));
    float s2 = zv.z / (1.f + expf(-zv.z));
    float s3 = zv.w / (1.f + expf(-zv.w));

    __half2* dst = (__half2*)(oh + row * DV) + 2 * lane;
    dst[0] = __floats2half2_rn(x.x * r * nw.x * s0, x.y * r * nw.y * s1);
    dst[1] = __floats2half2_rn(x.z * r * nw.z * s2, x.w * r * nw.w * s3);
}

// ---------------------------------------------------------------------------
// Launch: chunked pipeline, capture-clean fork/join, batch-merged launches.
// ---------------------------------------------------------------------------
extern "C" void kernel_launch(void* const* d_in, const int* in_sizes, int n_in,
                              void* d_out, int out_size)
{
    const float* hs      = (const float*)d_in[0];
    const float* W_qkv   = (const float*)d_in[1];
    const float* W_z     = (const float*)d_in[2];
    const float* W_b     = (const float*)d_in[3];
    const float* W_a     = (const float*)d_in[4];
    const float* conv_w  = (const float*)d_in[5];
    const float* dt_bias = (const float*)d_in[6];
    const float* A_log   = (const float*)d_in[7];
    const float* norm_w  = (const float*)d_in[8];
    const float* W_out   = (const float*)d_in[9];
    float* out = (float*)d_out;

    float *qkvba, *z, *q, *k, *v, *beta, *decay, *o, *Sst;
    __half *hs_h, *wqkvbaT, *wzT, *woutT, *oh;
    cudaGetSymbolAddress((void**)&qkvba,   g_qkvba);
    cudaGetSymbolAddress((void**)&z,       g_z);
    cudaGetSymbolAddress((void**)&q,       g_q);
    cudaGetSymbolAddress((void**)&k,       g_k);
    cudaGetSymbolAddress((void**)&v,       g_v);
    cudaGetSymbolAddress((void**)&beta,    g_beta);
    cudaGetSymbolAddress((void**)&decay,   g_decay);
    cudaGetSymbolAddress((void**)&o,       g_o);
    cudaGetSymbolAddress((void**)&Sst,     g_S);
    cudaGetSymbolAddress((void**)&hs_h,    g_hs_h);
    cudaGetSymbolAddress((void**)&wqkvbaT, g_wqkvbaT);
    cudaGetSymbolAddress((void**)&wzT,     g_wzT);
    cudaGetSymbolAddress((void**)&woutT,   g_woutT);
    cudaGetSymbolAddress((void**)&oh,      g_oh);

    static cudaStream_t s1 = nullptr, s2 = nullptr;
    static cudaEvent_t ev_root = nullptr, ev_in = nullptr, ev_wz = nullptr;
    static cudaEvent_t ev_feed[NCHUNK] = {}, ev_scan[NCHUNK] = {}, ev_z[NCHUNK] = {};
    static cudaEvent_t ev_done = nullptr, ev_s1done = nullptr;
    static bool init_done = false;
    if (!init_done) {
        cudaStreamCreateWithFlags(&s1, cudaStreamNonBlocking);
        cudaStreamCreateWithFlags(&s2, cudaStreamNonBlocking);
        cudaEventCreateWithFlags(&ev_root, cudaEventDisableTiming);
        cudaEventCreateWithFlags(&ev_in,   cudaEventDisableTiming);
        cudaEventCreateWithFlags(&ev_wz,   cudaEventDisableTiming);
        for (int c = 0; c < NCHUNK; c++) {
            cudaEventCreateWithFlags(&ev_feed[c], cudaEventDisableTiming);
            cudaEventCreateWithFlags(&ev_scan[c], cudaEventDisableTiming);
            cudaEventCreateWithFlags(&ev_z[c],    cudaEventDisableTiming);
        }
        cudaEventCreateWithFlags(&ev_done,   cudaEventDisableTiming);
        cudaEventCreateWithFlags(&ev_s1done, cudaEventDisableTiming);
        cudaFuncSetAttribute(gemm_f16_kernel,
                             cudaFuncAttributeMaxDynamicSharedMemorySize, GEMM_SMEM);
        init_done = true;
    }

    const cudaStream_t s0 = 0;
    dim3 tb32(32, 8);

    // ---- capture-clean fork: side streams join the graph FIRST ----
    cudaEventRecord(ev_root, s0);
    cudaStreamWaitEvent(s1, ev_root, 0);
    cudaStreamWaitEvent(s2, ev_root, 0);

    // ---- s2: wz / wout weight packs ----
    {
        dim3 gz(VALDIM / 32, DMODEL / 32);
        packT_f16_kernel<<<gz, tb32, 0, s2>>>(W_z, wzT, DMODEL, VALDIM);
        cudaEventRecord(ev_wz, s2);
        dim3 go(DMODEL / 32, VALDIM / 32);
        packT_f16_kernel<<<go, tb32, 0, s2>>>(W_out, woutT, VALDIM, DMODEL);
    }

    // ---- s0: input prepasses ----
    {
        size_t n4 = (size_t)BT * DMODEL / 4;
        cvt_f16_kernel<<<(unsigned)((n4 + 255) / 256), 256, 0, s0>>>(hs, hs_h, n4);
        dim3 gq(QBT_NP / 32, DMODEL / 32);
        pack_wqkvbaT_kernel<<<gq, tb32, 0, s0>>>(W_qkv, W_b, W_a, wqkvbaT);
        cudaEventRecord(ev_in, s0);
    }

    const long strideA_hs = (long)TLEN * DMODEL;   // batch stride in hs_h rows
    const long strideC_qb = (long)TLEN * QB_N;
    const long strideC_z  = (long)TLEN * VALDIM;
    const long strideA_oh = (long)TLEN * VALDIM;
    const long strideC_o  = (long)TLEN * DMODEL;

    // ---- s1: chunked feed pipeline (+ z chunk each iteration) ----
    cudaStreamWaitEvent(s1, ev_in, 0);
    cudaStreamWaitEvent(s1, ev_wz, 0);
    for (int c = 0; c < NCHUNK; c++) {
        const int t0 = c * TC;
        launch_gemm_b(hs_h + (size_t)t0 * DMODEL, wqkvbaT,
                      qkvba + (size_t)t0 * QB_N, TC, QB_N, DMODEL,
                      strideA_hs, strideC_qb, BATCH, s1);
        {
            size_t n = (size_t)(BATCH * TC) * CONVDIM;
            conv_silu_split_kernel<<<(unsigned)((n + 255) / 256), 256, 0, s1>>>(
                qkvba, conv_w, q, k, v, t0);
        }
        {
            int wgs = 4 * TC * NKH;
            l2norm_qk_kernel<<<(wgs + 7) / 8, 256, 0, s1>>>(q, k, t0);
        }
        beta_decay_kernel<<<(BATCH * TC * NVH + 255) / 256, 256, 0, s1>>>(
            qkvba, dt_bias, A_log, beta, decay, t0);
        cudaEventRecord(ev_feed[c], s1);

        launch_gemm_b(hs_h + (size_t)t0 * DMODEL, wzT,
                      z + (size_t)t0 * VALDIM, TC, VALDIM, DMODEL,
                      strideA_hs, strideC_z, BATCH, s1);
        cudaEventRecord(ev_z[c], s1);
    }
    cudaEventRecord(ev_s1done, s1);

    // ---- s0: scan chunks ----
    for (int c = 0; c < NCHUNK; c++) {
        cudaStreamWaitEvent(s0, ev_feed[c], 0);
        scan_kernel<<<BATCH * NVH * 2, 128, 0, s0>>>(
            q, k, v, decay, beta, o, Sst, c * TC, (c + 1) * TC);
        cudaEventRecord(ev_scan[c], s0);
    }

    // ---- s2: gate + out-projection per chunk ----
    for (int c = 0; c < NCHUNK; c++) {
        const int t0 = c * TC;
        cudaStreamWaitEvent(s2, ev_scan[c], 0);
        cudaStreamWaitEvent(s2, ev_z[c], 0);
        {
            int rows = BATCH * TC * NVH;
            gate_kernel<<<(rows + 7) / 8, 256, 0, s2>>>(o, z, norm_w, oh, t0);
        }
        launch_gemm_b(oh + (size_t)t0 * VALDIM, woutT,
                      out + (size_t)t0 * DMODEL, TC, DMODEL, VALDIM,
                      strideA_oh, strideC_o, BATCH, s2);
    }

    // ---- join everything back to s0 ----
    cudaEventRecord(ev_done, s2);
    cudaStreamWaitEvent(s0, ev_done, 0);
    cudaStreamWaitEvent(s0, ev_s1done, 0);
}